// round 9
// baseline (speedup 1.0000x reference)
#include <cuda_runtime.h>
#include <math.h>

// ---------------- problem constants ----------------
#define NLEV   16
#define TBL    524288u          // T = 2^19 entries per level
#define TMASK  (TBL - 1u)
#define HP1    2654435761u
#define HP2    805459861u

#define CAP    2097152          // expected N
#define KBITS  15
#define BINS   (1u << KBITS)    // 32768 morton buckets (1/32 cube side)
#define TILE   1024
#define NTILES (BINS / TILE)    // 32

typedef unsigned long long ull;

// MLP weights in constant memory (warp-uniform -> LDC, keeps LSU free)
__constant__ __align__(16) float cW1[32 * 64];
__constant__ __align__(16) float cW2[64 * 16];

// ---- static scratch (no dynamic allocation allowed) ----
__device__ unsigned g_keys[CAP];
__device__ unsigned g_perm[CAP];
__device__ float    g_sx[CAP];
__device__ float    g_sy[CAP];
__device__ float    g_sz[CAP];
__device__ unsigned g_hist[BINS];
__device__ unsigned g_offs[BINS];
__device__ unsigned g_part[NTILES];
__device__ __align__(16) float g_scratch[(size_t)CAP * 16];  // sorted-order rows

struct LevelParams {
    float    resf[NLEV];
    unsigned s[NLEV];
    unsigned dense[NLEV];
};

// ---------------- packed f32x2 helpers ----------------
__device__ __forceinline__ ull pack2(float v) {
    ull r; unsigned u = __float_as_uint(v);
    asm("mov.b64 %0, {%1,%1};" : "=l"(r) : "r"(u));
    return r;
}
__device__ __forceinline__ ull fma2(ull a, ull b, ull c) {
    ull d;
    asm("fma.rn.f32x2 %0, %1, %2, %3;" : "=l"(d) : "l"(a), "l"(b), "l"(c));
    return d;
}
__device__ __forceinline__ float2 unpack2(ull v) {
    unsigned lo, hi;
    asm("mov.b64 {%0,%1}, %2;" : "=r"(lo), "=r"(hi) : "l"(v));
    return make_float2(__uint_as_float(lo), __uint_as_float(hi));
}

// Dual-path paired gather, alignment-safe (R6 value-swap version: 708us baseline).
__device__ __forceinline__ void gather_pair(const float2* __restrict__ tab,
                                            unsigned a0, unsigned a1,
                                            unsigned adj,
                                            float& v0x, float& v0y,
                                            float& v1x, float& v1y) {
    const float4* pa = reinterpret_cast<const float4*>(tab + (a0 & ~1u));
    float qx, qy, qz, qw;
    asm volatile("{\n\t"
                 ".reg .pred p;\n\t"
                 "setp.ne.u32 p, %4, 0;\n\t"
                 "@p  ld.global.nc.v4.f32 {%0,%1,%2,%3}, [%5];\n\t"
                 "@!p ld.global.nc.v2.f32 {%0,%1}, [%6];\n\t"
                 "@!p ld.global.nc.v2.f32 {%2,%3}, [%7];\n\t"
                 "}"
                 : "=f"(qx), "=f"(qy), "=f"(qz), "=f"(qw)
                 : "r"(adj), "l"(pa), "l"(tab + a0), "l"(tab + a1));
    bool swap = (adj != 0u) && ((a0 & 1u) != 0u);
    v0x = swap ? qz : qx;
    v0y = swap ? qw : qy;
    v1x = swap ? qx : qz;
    v1y = swap ? qy : qw;
}

__device__ __forceinline__ float clip01(float v) {
    return fminf(fmaxf((v + 1.0f) * 0.5f, 0.0f), 1.0f);
}

// ---------------- morton (5 bits/axis) ----------------
__device__ __forceinline__ unsigned part1by2(unsigned x) {
    x &= 0x3ffu;
    x = (x | (x << 16)) & 0x030000FFu;
    x = (x | (x << 8))  & 0x0300F00Fu;
    x = (x | (x << 4))  & 0x030C30C3u;
    x = (x | (x << 2))  & 0x09249249u;
    return x;
}
__device__ __forceinline__ unsigned morton_key(float x, float y, float z) {
    unsigned ix = min((unsigned)(clip01(x) * 32.0f), 31u);
    unsigned iy = min((unsigned)(clip01(y) * 32.0f), 31u);
    unsigned iz = min((unsigned)(clip01(z) * 32.0f), 31u);
    return part1by2(ix) | (part1by2(iy) << 1) | (part1by2(iz) << 2);
}

// ---------------- sort pipeline ----------------
__global__ void k_zero_hist() {
    unsigned g = blockIdx.x * blockDim.x + threadIdx.x;
    if (g < BINS) g_hist[g] = 0u;
}
__global__ void k_keys_hist(const float* __restrict__ xyzs, int N) {
    int i = blockIdx.x * blockDim.x + threadIdx.x;
    if (i >= N) return;
    unsigned k = morton_key(xyzs[3 * i], xyzs[3 * i + 1], xyzs[3 * i + 2]);
    g_keys[i] = k;
    atomicAdd(&g_hist[k], 1u);
}
__global__ void k_scan_tiles() {
    __shared__ unsigned sm[TILE];
    unsigned t = threadIdx.x;
    unsigned g = blockIdx.x * TILE + t;
    unsigned v = g_hist[g];
    sm[t] = v;
    __syncthreads();
#pragma unroll
    for (unsigned d = 1; d < TILE; d <<= 1) {
        unsigned add = (t >= d) ? sm[t - d] : 0u;
        __syncthreads();
        sm[t] += add;
        __syncthreads();
    }
    g_offs[g] = sm[t] - v;
    if (t == TILE - 1) g_part[blockIdx.x] = sm[t];
}
__global__ void k_scan_part() {
    __shared__ unsigned sm[NTILES];
    unsigned t = threadIdx.x;
    unsigned v = g_part[t];
    sm[t] = v;
    __syncthreads();
#pragma unroll
    for (unsigned d = 1; d < NTILES; d <<= 1) {
        unsigned add = (t >= d) ? sm[t - d] : 0u;
        __syncthreads();
        sm[t] += add;
        __syncthreads();
    }
    g_part[t] = sm[t] - v;
}
__global__ void k_scatter(const float* __restrict__ xyzs, int N) {
    int i = blockIdx.x * blockDim.x + threadIdx.x;
    if (i >= N) return;
    unsigned k   = g_keys[i];
    unsigned pos = atomicAdd(&g_offs[k], 1u) + g_part[k >> 10];
    g_perm[pos] = (unsigned)i;
    g_sx[pos] = xyzs[3 * i];
    g_sy[pos] = xyzs[3 * i + 1];
    g_sz[pos] = xyzs[3 * i + 2];
}

// ---------------- fused kernel: hashgrid encode + MLP (R6 compute) ----------------
#define BLK 256

__global__ void __launch_bounds__(BLK, 3)
hashgrid_mlp_kernel(const float* __restrict__ xyzs,
                    const float* __restrict__ tables,
                    float* __restrict__ out,
                    int N, int sorted_mode, LevelParams lp)
{
    // 32KB buffer: phase 1 = senc[16][BLK] float2 (thread-private column),
    //              phase 2 = output staging (16 floats/thread sorted mode,
    //                                        15 floats/thread direct mode)
    __shared__ __align__(16) char sbuf[NLEV * BLK * 8];
    float2* senc = reinterpret_cast<float2*>(sbuf);
    float*  sout = reinterpret_cast<float*>(sbuf);

    int i = blockIdx.x * BLK + threadIdx.x;
    bool active = (i < N);
    unsigned tid = threadIdx.x;

    float o[16];

    if (active) {
        float x, y, z;
        if (sorted_mode) {
            x = g_sx[i]; y = g_sy[i]; z = g_sz[i];
        } else {
            x = xyzs[3 * i]; y = xyzs[3 * i + 1]; z = xyzs[3 * i + 2];
        }
        float x01 = clip01(x), y01 = clip01(y), z01 = clip01(z);

        // ---------------- gather phase: enc -> smem ----------------
#pragma unroll
        for (int l = 0; l < NLEV; l++) {
            const float2* __restrict__ tab =
                reinterpret_cast<const float2*>(tables) + (size_t)l * TBL;

            float rf = lp.resf[l];
            float px = x01 * rf, py = y01 * rf, pz = z01 * rf;
            float fpx = floorf(px), fpy = floorf(py), fpz = floorf(pz);
            float fx = px - fpx, fy = py - fpy, fz = pz - fpz;
            unsigned ix = (unsigned)fpx, iy = (unsigned)fpy, iz = (unsigned)fpz;
            float wx0 = 1.0f - fx, wy0 = 1.0f - fy, wz0 = 1.0f - fz;

            unsigned i0a[4], i1a[4];
            float    wyz[4];
            if (lp.dense[l]) {
                unsigned s = lp.s[l];
#pragma unroll
                for (int k = 0; k < 2; k++) {
#pragma unroll
                    for (int j = 0; j < 2; j++) {
                        unsigned a = s * ((iy + (unsigned)j) + s * (iz + (unsigned)k));
                        int c = k * 2 + j;
                        i0a[c] = ix + a;
                        i1a[c] = ix + 1u + a;
                        wyz[c] = (j ? fy : wy0) * (k ? fz : wz0);
                    }
                }
            } else {
                unsigned hy0 = iy * HP1;
                unsigned hz0 = iz * HP2;
#pragma unroll
                for (int k = 0; k < 2; k++) {
#pragma unroll
                    for (int j = 0; j < 2; j++) {
                        unsigned a = (hy0 + (j ? HP1 : 0u)) ^ (hz0 + (k ? HP2 : 0u));
                        int c = k * 2 + j;
                        i0a[c] = (ix ^ a) & TMASK;
                        i1a[c] = ((ix + 1u) ^ a) & TMASK;
                        wyz[c] = (j ? fy : wy0) * (k ? fz : wz0);
                    }
                }
            }

            float v0x[4], v0y[4], v1x[4], v1y[4];
#pragma unroll
            for (int c = 0; c < 4; c++) {
                unsigned adj = ((i0a[c] ^ i1a[c]) == 1u) ? 1u : 0u;
                gather_pair(tab, i0a[c], i1a[c], adj,
                            v0x[c], v0y[c], v1x[c], v1y[c]);
            }

            float e0 = 0.0f, e1 = 0.0f;
#pragma unroll
            for (int c = 0; c < 4; c++) {
                float w0 = wx0 * wyz[c];
                float w1 = fx  * wyz[c];
                e0 = fmaf(w0, v0x[c], fmaf(w1, v1x[c], e0));
                e1 = fmaf(w0, v0y[c], fmaf(w1, v1y[c], e1));
            }
            senc[l * BLK + tid] = make_float2(e0, e1);
        }

        // ---------------- MLP: two 32-wide hidden chunks ----------------
        ull op[8];
#pragma unroll
        for (int j = 0; j < 8; j++) op[j] = 0ull;

#pragma unroll
        for (int half = 0; half < 2; half++) {
            ull hp[16];
#pragma unroll
            for (int j = 0; j < 16; j++) hp[j] = 0ull;

#pragma unroll
            for (int ip = 0; ip < 16; ip++) {
                float2 e = senc[ip * BLK + tid];
                ull e0 = pack2(e.x), e1 = pack2(e.y);
                const ulonglong2* r0 = reinterpret_cast<const ulonglong2*>(
                    cW1 + (2 * ip) * 64 + 32 * half);
                const ulonglong2* r1 = reinterpret_cast<const ulonglong2*>(
                    cW1 + (2 * ip + 1) * 64 + 32 * half);
#pragma unroll
                for (int j = 0; j < 8; j++) {
                    ulonglong2 wa = r0[j];
                    ulonglong2 wb = r1[j];
                    hp[2 * j]     = fma2(e0, wa.x, hp[2 * j]);
                    hp[2 * j + 1] = fma2(e0, wa.y, hp[2 * j + 1]);
                    hp[2 * j]     = fma2(e1, wb.x, hp[2 * j]);
                    hp[2 * j + 1] = fma2(e1, wb.y, hp[2 * j + 1]);
                }
            }

#pragma unroll
            for (int j = 0; j < 16; j++) {
                float2 p = unpack2(hp[j]);
                ull eh0 = pack2(fmaxf(p.x, 0.0f));
                ull eh1 = pack2(fmaxf(p.y, 0.0f));
                int i2 = 32 * half + 2 * j;
                const ulonglong2* w0 =
                    reinterpret_cast<const ulonglong2*>(cW2 + i2 * 16);
                const ulonglong2* w1 = w0 + 4;
#pragma unroll
                for (int q = 0; q < 4; q++) {
                    ulonglong2 a = w0[q];
                    ulonglong2 b = w1[q];
                    op[2 * q]     = fma2(eh0, a.x, op[2 * q]);
                    op[2 * q + 1] = fma2(eh0, a.y, op[2 * q + 1]);
                    op[2 * q]     = fma2(eh1, b.x, op[2 * q]);
                    op[2 * q + 1] = fma2(eh1, b.y, op[2 * q + 1]);
                }
            }
        }

#pragma unroll
        for (int j = 0; j < 8; j++) {
            float2 p = unpack2(op[j]);
            o[2 * j]     = p.x;
            o[2 * j + 1] = p.y;
        }
        o[0] = __expf(o[0]);
    }

    __syncthreads();                     // senc dead -> reuse buffer

    int base = blockIdx.x * BLK;
    int nPts = min(BLK, N - base);

    if (sorted_mode) {
        // stage full 16-float rows, cooperative float4 store to scratch
        if (active) {
#pragma unroll
            for (int k = 0; k < 16; k++) sout[tid * 16 + k] = o[k];
        }
        __syncthreads();
        if (nPts <= 0) return;
        float4* dst = reinterpret_cast<float4*>(g_scratch) + (size_t)base * 4;
        const float4* s4 = reinterpret_cast<const float4*>(sout);
        int n4 = nPts * 4;
        for (int t = tid; t < n4; t += BLK) dst[t] = s4[t];
    } else {
        if (active) {
            out[i] = o[0];
#pragma unroll
            for (int k = 0; k < 15; k++) sout[tid * 15 + k] = o[k + 1];
        }
        __syncthreads();
        if (nPts <= 0) return;
        float* gbase = out + (size_t)N + (size_t)base * 15;
        int total = nPts * 15;
        if (nPts == BLK && ((((size_t)gbase) & 15u) == 0)) {
            float4* g4 = reinterpret_cast<float4*>(gbase);
            const float4* s4 = reinterpret_cast<const float4*>(sout);
            int n4 = total / 4;
            for (int t = tid; t < n4; t += BLK) g4[t] = s4[t];
        } else {
            for (int t = tid; t < total; t += BLK) gbase[t] = sout[t];
        }
    }
}

// ---------------- unscatter: sorted scratch rows -> final layout ----------------
__global__ void k_unscatter(float* __restrict__ out, int N)
{
    int i = blockIdx.x * blockDim.x + threadIdx.x;
    if (i >= N) return;
    unsigned pid = g_perm[i];
    const float4* row = reinterpret_cast<const float4*>(g_scratch) + (size_t)i * 4;
    float4 a = row[0], b = row[1], c = row[2], d = row[3];
    out[pid] = a.x;
    float* g = out + (size_t)N + (size_t)pid * 15;
    __stcs(g + 0,  a.y); __stcs(g + 1,  a.z); __stcs(g + 2,  a.w);
    __stcs(g + 3,  b.x); __stcs(g + 4,  b.y); __stcs(g + 5,  b.z);
    __stcs(g + 6,  b.w); __stcs(g + 7,  c.x); __stcs(g + 8,  c.y);
    __stcs(g + 9,  c.z); __stcs(g + 10, c.w); __stcs(g + 11, d.x);
    __stcs(g + 12, d.y); __stcs(g + 13, d.z); __stcs(g + 14, d.w);
}

// ---------------- host ----------------
static LevelParams make_level_params()
{
    LevelParams lp;
    double pls = exp(log(2048.0 / 16.0) / (double)(NLEV - 1));
    for (int l = 0; l < NLEV; l++) {
        int r = (int)ceil(16.0 * pow(pls, (double)l));
        lp.resf[l]  = (float)r;
        lp.s[l]     = (unsigned)(r + 1);
        long long s = (long long)(r + 1);
        lp.dense[l] = (s * s * s <= (long long)TBL) ? 1u : 0u;
    }
    return lp;
}

extern "C" void kernel_launch(void* const* d_in, const int* in_sizes, int n_in,
                              void* d_out, int out_size)
{
    (void)n_in; (void)out_size;
    const float* xyzs   = (const float*)d_in[0];
    const float* tables = (const float*)d_in[1];
    int N = in_sizes[0] / 3;

    cudaMemcpyToSymbolAsync(cW1, d_in[2], 32 * 64 * sizeof(float), 0,
                            cudaMemcpyDeviceToDevice, 0);
    cudaMemcpyToSymbolAsync(cW2, d_in[3], 64 * 16 * sizeof(float), 0,
                            cudaMemcpyDeviceToDevice, 0);

    LevelParams lp = make_level_params();

    int sorted = (N <= CAP) ? 1 : 0;
    int gridN = (N + BLK - 1) / BLK;

    if (sorted) {
        k_zero_hist<<<BINS / 256, 256>>>();
        k_keys_hist<<<gridN, 256>>>(xyzs, N);
        k_scan_tiles<<<NTILES, TILE>>>();
        k_scan_part<<<1, NTILES>>>();
        k_scatter<<<gridN, 256>>>(xyzs, N);
    }

    hashgrid_mlp_kernel<<<gridN, BLK>>>(xyzs, tables, (float*)d_out,
                                        N, sorted, lp);

    if (sorted) {
        k_unscatter<<<gridN, 256>>>((float*)d_out, N);
    }
}

// round 10
// speedup vs baseline: 1.2035x; 1.2035x over previous
#include <cuda_runtime.h>
#include <math.h>

// ---------------- problem constants ----------------
#define NLEV   16
#define TBL    524288u          // T = 2^19 entries per level
#define TMASK  (TBL - 1u)
#define HP1    2654435761u
#define HP2    805459861u

typedef unsigned long long ull;

// MLP weights in constant memory
__constant__ __align__(16) float cW1[32 * 64];
__constant__ __align__(16) float cW2[64 * 16];

struct LevelParams {
    float    resf[NLEV];
    unsigned s[NLEV];
    unsigned dense[NLEV];
};

// ---------------- packed f32x2 helpers ----------------
__device__ __forceinline__ ull pack2(float v) {
    ull r; unsigned u = __float_as_uint(v);
    asm("mov.b64 %0, {%1,%1};" : "=l"(r) : "r"(u));
    return r;
}
__device__ __forceinline__ ull fma2(ull a, ull b, ull c) {
    ull d;
    asm("fma.rn.f32x2 %0, %1, %2, %3;" : "=l"(d) : "l"(a), "l"(b), "l"(c));
    return d;
}
__device__ __forceinline__ float2 unpack2(ull v) {
    unsigned lo, hi;
    asm("mov.b64 {%0,%1}, %2;" : "=r"(lo), "=r"(hi) : "l"(v));
    return make_float2(__uint_as_float(lo), __uint_as_float(hi));
}

// Dual-path paired gather, alignment-safe (R6-proven).
__device__ __forceinline__ void gather_pair(const float2* __restrict__ tab,
                                            unsigned a0, unsigned a1,
                                            unsigned adj,
                                            float& v0x, float& v0y,
                                            float& v1x, float& v1y) {
    const float4* pa = reinterpret_cast<const float4*>(tab + (a0 & ~1u));
    float qx, qy, qz, qw;
    asm volatile("{\n\t"
                 ".reg .pred p;\n\t"
                 "setp.ne.u32 p, %4, 0;\n\t"
                 "@p  ld.global.nc.v4.f32 {%0,%1,%2,%3}, [%5];\n\t"
                 "@!p ld.global.nc.v2.f32 {%0,%1}, [%6];\n\t"
                 "@!p ld.global.nc.v2.f32 {%2,%3}, [%7];\n\t"
                 "}"
                 : "=f"(qx), "=f"(qy), "=f"(qz), "=f"(qw)
                 : "r"(adj), "l"(pa), "l"(tab + a0), "l"(tab + a1));
    bool swap = (adj != 0u) && ((a0 & 1u) != 0u);
    v0x = swap ? qz : qx;
    v0y = swap ? qw : qy;
    v1x = swap ? qx : qz;
    v1y = swap ? qy : qw;
}

__device__ __forceinline__ float clip01(float v) {
    return fminf(fmaxf((v + 1.0f) * 0.5f, 0.0f), 1.0f);
}

// ---------------- fused kernel: 2 points per thread ----------------
#define BLK 128              // threads per block
#define PPB 256              // points per block (2 per thread)

__global__ void __launch_bounds__(BLK, 3)
hashgrid_mlp_kernel(const float* __restrict__ xyzs,
                    const float* __restrict__ tables,
                    float* __restrict__ out,
                    int N, LevelParams lp)
{
    // 32KB buffer: phase 1 = senc[16][PPB] float2 (thread-private columns),
    //              phase 2 = sgeo[PPB*15] float   (coalesced geo staging)
    __shared__ __align__(16) char sbuf[NLEV * PPB * 8];
    float2* senc = reinterpret_cast<float2*>(sbuf);
    float*  sgeo = reinterpret_cast<float*>(sbuf);

    unsigned tid = threadIdx.x;
    int base = blockIdx.x * PPB;
    int pa = base + (int)tid;            // point A
    int pb = pa + BLK;                   // point B
    bool actA = (pa < N);
    bool actB = (pb < N);
    // clamped load indices: inactive points compute garbage safely
    int la = min(pa, N - 1);
    int lb = min(pb, N - 1);

    float x01[2], y01[2], z01[2];
    x01[0] = clip01(xyzs[3 * la + 0]);
    y01[0] = clip01(xyzs[3 * la + 1]);
    z01[0] = clip01(xyzs[3 * la + 2]);
    x01[1] = clip01(xyzs[3 * lb + 0]);
    y01[1] = clip01(xyzs[3 * lb + 1]);
    z01[1] = clip01(xyzs[3 * lb + 2]);

    // ---------------- gather phase: enc -> smem, both points ----------------
#pragma unroll
    for (int l = 0; l < NLEV; l++) {
        const float2* __restrict__ tab =
            reinterpret_cast<const float2*>(tables) + (size_t)l * TBL;
        float rf = lp.resf[l];
        unsigned sdense = lp.s[l];
        unsigned isdense = lp.dense[l];

#pragma unroll
        for (int pt = 0; pt < 2; pt++) {
            float px = x01[pt] * rf, py = y01[pt] * rf, pz = z01[pt] * rf;
            float fpx = floorf(px), fpy = floorf(py), fpz = floorf(pz);
            float fx = px - fpx, fy = py - fpy, fz = pz - fpz;
            unsigned ix = (unsigned)fpx, iy = (unsigned)fpy, iz = (unsigned)fpz;
            float wx0 = 1.0f - fx, wy0 = 1.0f - fy, wz0 = 1.0f - fz;

            unsigned i0a[4], i1a[4];
            float    wyz[4];
            if (isdense) {
                unsigned s = sdense;
#pragma unroll
                for (int k = 0; k < 2; k++) {
#pragma unroll
                    for (int j = 0; j < 2; j++) {
                        unsigned a = s * ((iy + (unsigned)j) + s * (iz + (unsigned)k));
                        int c = k * 2 + j;
                        i0a[c] = ix + a;
                        i1a[c] = ix + 1u + a;
                        wyz[c] = (j ? fy : wy0) * (k ? fz : wz0);
                    }
                }
            } else {
                unsigned hy0 = iy * HP1;
                unsigned hz0 = iz * HP2;
#pragma unroll
                for (int k = 0; k < 2; k++) {
#pragma unroll
                    for (int j = 0; j < 2; j++) {
                        unsigned a = (hy0 + (j ? HP1 : 0u)) ^ (hz0 + (k ? HP2 : 0u));
                        int c = k * 2 + j;
                        i0a[c] = (ix ^ a) & TMASK;
                        i1a[c] = ((ix + 1u) ^ a) & TMASK;
                        wyz[c] = (j ? fy : wy0) * (k ? fz : wz0);
                    }
                }
            }

            float v0x[4], v0y[4], v1x[4], v1y[4];
#pragma unroll
            for (int c = 0; c < 4; c++) {
                unsigned adj = ((i0a[c] ^ i1a[c]) == 1u) ? 1u : 0u;
                gather_pair(tab, i0a[c], i1a[c], adj,
                            v0x[c], v0y[c], v1x[c], v1y[c]);
            }

            float e0 = 0.0f, e1 = 0.0f;
#pragma unroll
            for (int c = 0; c < 4; c++) {
                float w0 = wx0 * wyz[c];
                float w1 = fx  * wyz[c];
                e0 = fmaf(w0, v0x[c], fmaf(w1, v1x[c], e0));
                e1 = fmaf(w0, v0y[c], fmaf(w1, v1y[c], e1));
            }
            senc[l * PPB + tid + pt * BLK] = make_float2(e0, e1);
        }
    }

    // ---------------- MLP: both points share every weight load ----------------
    ull opA[8], opB[8];
#pragma unroll
    for (int j = 0; j < 8; j++) { opA[j] = 0ull; opB[j] = 0ull; }

#pragma unroll
    for (int half = 0; half < 2; half++) {
        ull hpA[16], hpB[16];
#pragma unroll
        for (int j = 0; j < 16; j++) { hpA[j] = 0ull; hpB[j] = 0ull; }

#pragma unroll
        for (int ip = 0; ip < 16; ip++) {
            float2 eA = senc[ip * PPB + tid];
            float2 eB = senc[ip * PPB + tid + BLK];
            ull a0 = pack2(eA.x), a1 = pack2(eA.y);
            ull b0 = pack2(eB.x), b1 = pack2(eB.y);
            const ulonglong2* r0 = reinterpret_cast<const ulonglong2*>(
                cW1 + (2 * ip) * 64 + 32 * half);
            const ulonglong2* r1 = reinterpret_cast<const ulonglong2*>(
                cW1 + (2 * ip + 1) * 64 + 32 * half);
#pragma unroll
            for (int j = 0; j < 8; j++) {
                ulonglong2 wa = r0[j];       // one LDC.128 feeds both points
                ulonglong2 wb = r1[j];
                hpA[2 * j]     = fma2(a0, wa.x, hpA[2 * j]);
                hpA[2 * j + 1] = fma2(a0, wa.y, hpA[2 * j + 1]);
                hpA[2 * j]     = fma2(a1, wb.x, hpA[2 * j]);
                hpA[2 * j + 1] = fma2(a1, wb.y, hpA[2 * j + 1]);
                hpB[2 * j]     = fma2(b0, wa.x, hpB[2 * j]);
                hpB[2 * j + 1] = fma2(b0, wa.y, hpB[2 * j + 1]);
                hpB[2 * j]     = fma2(b1, wb.x, hpB[2 * j]);
                hpB[2 * j + 1] = fma2(b1, wb.y, hpB[2 * j + 1]);
            }
        }

        // relu + layer-2 accumulation, shared weight loads
#pragma unroll
        for (int j = 0; j < 16; j++) {
            float2 pA = unpack2(hpA[j]);
            float2 pB = unpack2(hpB[j]);
            ull ea0 = pack2(fmaxf(pA.x, 0.0f));
            ull ea1 = pack2(fmaxf(pA.y, 0.0f));
            ull eb0 = pack2(fmaxf(pB.x, 0.0f));
            ull eb1 = pack2(fmaxf(pB.y, 0.0f));
            int i2 = 32 * half + 2 * j;
            const ulonglong2* w0 =
                reinterpret_cast<const ulonglong2*>(cW2 + i2 * 16);
            const ulonglong2* w1 = w0 + 4;
#pragma unroll
            for (int q = 0; q < 4; q++) {
                ulonglong2 a = w0[q];
                ulonglong2 b = w1[q];
                opA[2 * q]     = fma2(ea0, a.x, opA[2 * q]);
                opA[2 * q + 1] = fma2(ea0, a.y, opA[2 * q + 1]);
                opA[2 * q]     = fma2(ea1, b.x, opA[2 * q]);
                opA[2 * q + 1] = fma2(ea1, b.y, opA[2 * q + 1]);
                opB[2 * q]     = fma2(eb0, a.x, opB[2 * q]);
                opB[2 * q + 1] = fma2(eb0, a.y, opB[2 * q + 1]);
                opB[2 * q]     = fma2(eb1, b.x, opB[2 * q]);
                opB[2 * q + 1] = fma2(eb1, b.y, opB[2 * q + 1]);
            }
        }
    }

    // sigma stores (coalesced within each half-warp group)
    if (actA) out[pa] = __expf(unpack2(opA[0]).x);
    if (actB) out[pb] = __expf(unpack2(opB[0]).x);

    __syncthreads();                     // senc dead -> reuse for geo staging

    // stage geo rows: thread writes local rows tid and tid+BLK
    {
        float2 p0 = unpack2(opA[0]);
        sgeo[tid * 15 + 0] = p0.y;
#pragma unroll
        for (int j = 1; j < 8; j++) {
            float2 p = unpack2(opA[j]);
            sgeo[tid * 15 + 2 * j - 1] = p.x;
            sgeo[tid * 15 + 2 * j]     = p.y;
        }
        float2 q0 = unpack2(opB[0]);
        sgeo[(tid + BLK) * 15 + 0] = q0.y;
#pragma unroll
        for (int j = 1; j < 8; j++) {
            float2 p = unpack2(opB[j]);
            sgeo[(tid + BLK) * 15 + 2 * j - 1] = p.x;
            sgeo[(tid + BLK) * 15 + 2 * j]     = p.y;
        }
    }
    __syncthreads();

    // cooperative coalesced store of this block's geo region
    int nPts = min(PPB, N - base);
    if (nPts <= 0) return;
    float* gbase = out + (size_t)N + (size_t)base * 15;
    int total = nPts * 15;
    if (nPts == PPB && ((((size_t)gbase) & 15u) == 0)) {
        float4* g4 = reinterpret_cast<float4*>(gbase);
        const float4* s4 = reinterpret_cast<const float4*>(sgeo);
        int n4 = total / 4;  // 960
        for (int t = tid; t < n4; t += BLK) g4[t] = s4[t];
    } else {
        for (int t = tid; t < total; t += BLK) gbase[t] = sgeo[t];
    }
}

// ---------------- host ----------------
static LevelParams make_level_params()
{
    LevelParams lp;
    double pls = exp(log(2048.0 / 16.0) / (double)(NLEV - 1));
    for (int l = 0; l < NLEV; l++) {
        int r = (int)ceil(16.0 * pow(pls, (double)l));
        lp.resf[l]  = (float)r;
        lp.s[l]     = (unsigned)(r + 1);
        long long s = (long long)(r + 1);
        lp.dense[l] = (s * s * s <= (long long)TBL) ? 1u : 0u;
    }
    return lp;
}

extern "C" void kernel_launch(void* const* d_in, const int* in_sizes, int n_in,
                              void* d_out, int out_size)
{
    (void)n_in; (void)out_size;
    const float* xyzs   = (const float*)d_in[0];
    const float* tables = (const float*)d_in[1];
    int N = in_sizes[0] / 3;

    cudaMemcpyToSymbolAsync(cW1, d_in[2], 32 * 64 * sizeof(float), 0,
                            cudaMemcpyDeviceToDevice, 0);
    cudaMemcpyToSymbolAsync(cW2, d_in[3], 64 * 16 * sizeof(float), 0,
                            cudaMemcpyDeviceToDevice, 0);

    LevelParams lp = make_level_params();

    int gridN = (N + PPB - 1) / PPB;
    hashgrid_mlp_kernel<<<gridN, BLK>>>(xyzs, tables, (float*)d_out, N, lp);
}

// round 11
// speedup vs baseline: 1.2338x; 1.0251x over previous
#include <cuda_runtime.h>
#include <math.h>

// ---------------- problem constants ----------------
#define NLEV   16
#define TBL    524288u          // T = 2^19 entries per level
#define TMASK  (TBL - 1u)
#define HP1    2654435761u
#define HP2    805459861u

typedef unsigned long long ull;

// MLP weights in constant memory (warp-uniform)
__constant__ __align__(16) float cW1[32 * 64];
__constant__ __align__(16) float cW2[64 * 16];

struct LevelParams {
    float    resf[NLEV];
    unsigned s[NLEV];
    unsigned dense[NLEV];
};

// ---------------- packed f32x2 helpers ----------------
__device__ __forceinline__ ull pack2(float v) {
    ull r; unsigned u = __float_as_uint(v);
    asm("mov.b64 %0, {%1,%1};" : "=l"(r) : "r"(u));
    return r;
}
__device__ __forceinline__ ull fma2(ull a, ull b, ull c) {
    ull d;
    asm("fma.rn.f32x2 %0, %1, %2, %3;" : "=l"(d) : "l"(a), "l"(b), "l"(c));
    return d;
}
__device__ __forceinline__ float2 unpack2(ull v) {
    unsigned lo, hi;
    asm("mov.b64 {%0,%1}, %2;" : "=r"(lo), "=r"(hi) : "l"(v));
    return make_float2(__uint_as_float(lo), __uint_as_float(hi));
}

// Dual-path paired gather, alignment-safe (proven since R4).
__device__ __forceinline__ void gather_pair(const float2* __restrict__ tab,
                                            unsigned a0, unsigned a1,
                                            unsigned adj,
                                            float& v0x, float& v0y,
                                            float& v1x, float& v1y) {
    const float4* pa = reinterpret_cast<const float4*>(tab + (a0 & ~1u));
    float qx, qy, qz, qw;
    asm volatile("{\n\t"
                 ".reg .pred p;\n\t"
                 "setp.ne.u32 p, %4, 0;\n\t"
                 "@p  ld.global.nc.v4.f32 {%0,%1,%2,%3}, [%5];\n\t"
                 "@!p ld.global.nc.v2.f32 {%0,%1}, [%6];\n\t"
                 "@!p ld.global.nc.v2.f32 {%2,%3}, [%7];\n\t"
                 "}"
                 : "=f"(qx), "=f"(qy), "=f"(qz), "=f"(qw)
                 : "r"(adj), "l"(pa), "l"(tab + a0), "l"(tab + a1));
    bool swap = (adj != 0u) && ((a0 & 1u) != 0u);
    v0x = swap ? qz : qx;
    v0y = swap ? qw : qy;
    v1x = swap ? qx : qz;
    v1y = swap ? qy : qw;
}

__device__ __forceinline__ float clip01(float v) {
    return fminf(fmaxf((v + 1.0f) * 0.5f, 0.0f), 1.0f);
}

// ---------------- fused kernel: hashgrid encode + MLP ----------------
#define BLK 256

__global__ void __launch_bounds__(BLK, 2)      // 128-reg cap: room, no spills
hashgrid_mlp_kernel(const float* __restrict__ xyzs,
                    const float* __restrict__ tables,
                    float* __restrict__ out,
                    int N, LevelParams lp)
{
    __shared__ __align__(16) float sgeo[BLK * 15];   // geo staging only

    int pid = blockIdx.x * BLK + threadIdx.x;
    bool active = (pid < N);
    unsigned tid = threadIdx.x;

    float sigma = 0.0f;
    ull op[8];
#pragma unroll
    for (int j = 0; j < 8; j++) op[j] = 0ull;

    if (active) {
        float x = xyzs[3 * pid + 0];
        float y = xyzs[3 * pid + 1];
        float z = xyzs[3 * pid + 2];
        float x01 = clip01(x), y01 = clip01(y), z01 = clip01(z);

        float enc[32];

        // unroll 2: bounds the LDG front-batch (cross-CTA L1tex-queue
        // contention grows with oe*MLP_p1) while keeping dual-issue ILP.
#pragma unroll 2
        for (int l = 0; l < NLEV; l++) {
            const float2* __restrict__ tab =
                reinterpret_cast<const float2*>(tables) + (size_t)l * TBL;

            float rf = lp.resf[l];
            float px = x01 * rf, py = y01 * rf, pz = z01 * rf;
            float fpx = floorf(px), fpy = floorf(py), fpz = floorf(pz);
            float fx = px - fpx, fy = py - fpy, fz = pz - fpz;
            unsigned ix = (unsigned)fpx, iy = (unsigned)fpy, iz = (unsigned)fpz;
            float wx0 = 1.0f - fx, wy0 = 1.0f - fy, wz0 = 1.0f - fz;

            unsigned i0a[4], i1a[4];
            float    wyz[4];
            if (lp.dense[l]) {
                unsigned s = lp.s[l];
#pragma unroll
                for (int k = 0; k < 2; k++) {
#pragma unroll
                    for (int j = 0; j < 2; j++) {
                        unsigned a = s * ((iy + (unsigned)j) + s * (iz + (unsigned)k));
                        int c = k * 2 + j;
                        i0a[c] = ix + a;
                        i1a[c] = ix + 1u + a;
                        wyz[c] = (j ? fy : wy0) * (k ? fz : wz0);
                    }
                }
            } else {
                unsigned hy0 = iy * HP1;
                unsigned hz0 = iz * HP2;
#pragma unroll
                for (int k = 0; k < 2; k++) {
#pragma unroll
                    for (int j = 0; j < 2; j++) {
                        unsigned a = (hy0 + (j ? HP1 : 0u)) ^ (hz0 + (k ? HP2 : 0u));
                        int c = k * 2 + j;
                        i0a[c] = (ix ^ a) & TMASK;
                        i1a[c] = ((ix + 1u) ^ a) & TMASK;
                        wyz[c] = (j ? fy : wy0) * (k ? fz : wz0);
                    }
                }
            }

            float v0x[4], v0y[4], v1x[4], v1y[4];
#pragma unroll
            for (int c = 0; c < 4; c++) {
                unsigned adj = ((i0a[c] ^ i1a[c]) == 1u) ? 1u : 0u;
                gather_pair(tab, i0a[c], i1a[c], adj,
                            v0x[c], v0y[c], v1x[c], v1y[c]);
            }

            float e0 = 0.0f, e1 = 0.0f;
#pragma unroll
            for (int c = 0; c < 4; c++) {
                float w0 = wx0 * wyz[c];
                float w1 = fx  * wyz[c];
                e0 = fmaf(w0, v0x[c], fmaf(w1, v1x[c], e0));
                e1 = fmaf(w0, v0y[c], fmaf(w1, v1y[c], e1));
            }
            enc[2 * l]     = e0;
            enc[2 * l + 1] = e1;
        }

        // ---------------- MLP: two 32-wide hidden chunks (regs, no smem) ----
#pragma unroll
        for (int half = 0; half < 2; half++) {
            ull hp[16];
#pragma unroll
            for (int j = 0; j < 16; j++) hp[j] = 0ull;

#pragma unroll
            for (int ip = 0; ip < 16; ip++) {
                ull e0 = pack2(enc[2 * ip]);
                ull e1 = pack2(enc[2 * ip + 1]);
                const ulonglong2* r0 = reinterpret_cast<const ulonglong2*>(
                    cW1 + (2 * ip) * 64 + 32 * half);
                const ulonglong2* r1 = reinterpret_cast<const ulonglong2*>(
                    cW1 + (2 * ip + 1) * 64 + 32 * half);
#pragma unroll
                for (int j = 0; j < 8; j++) {
                    ulonglong2 wa = r0[j];
                    ulonglong2 wb = r1[j];
                    hp[2 * j]     = fma2(e0, wa.x, hp[2 * j]);
                    hp[2 * j + 1] = fma2(e0, wa.y, hp[2 * j + 1]);
                    hp[2 * j]     = fma2(e1, wb.x, hp[2 * j]);
                    hp[2 * j + 1] = fma2(e1, wb.y, hp[2 * j + 1]);
                }
            }

            // relu + layer-2 accumulation, consuming hp immediately
#pragma unroll
            for (int j = 0; j < 16; j++) {
                float2 p = unpack2(hp[j]);
                ull eh0 = pack2(fmaxf(p.x, 0.0f));
                ull eh1 = pack2(fmaxf(p.y, 0.0f));
                int i2 = 32 * half + 2 * j;
                const ulonglong2* w0 =
                    reinterpret_cast<const ulonglong2*>(cW2 + i2 * 16);
                const ulonglong2* w1 = w0 + 4;
#pragma unroll
                for (int q = 0; q < 4; q++) {
                    ulonglong2 a = w0[q];
                    ulonglong2 b = w1[q];
                    op[2 * q]     = fma2(eh0, a.x, op[2 * q]);
                    op[2 * q + 1] = fma2(eh0, a.y, op[2 * q + 1]);
                    op[2 * q]     = fma2(eh1, b.x, op[2 * q]);
                    op[2 * q + 1] = fma2(eh1, b.y, op[2 * q + 1]);
                }
            }
        }

        sigma = __expf(unpack2(op[0]).x);
        out[pid] = sigma;                // coalesced sigma store
    }

    // stage geo rows in smem (writes before any reader; single sync below)
    if (active) {
        float2 p0 = unpack2(op[0]);
        sgeo[tid * 15 + 0] = p0.y;
#pragma unroll
        for (int j = 1; j < 8; j++) {
            float2 p = unpack2(op[j]);
            sgeo[tid * 15 + 2 * j - 1] = p.x;
            sgeo[tid * 15 + 2 * j]     = p.y;
        }
    }
    __syncthreads();

    // cooperative coalesced store of this block's geo region
    int base = blockIdx.x * BLK;
    int nPts = min(BLK, N - base);
    if (nPts <= 0) return;
    float* gbase = out + (size_t)N + (size_t)base * 15;
    int total = nPts * 15;
    if (nPts == BLK && ((((size_t)gbase) & 15u) == 0)) {
        float4* g4 = reinterpret_cast<float4*>(gbase);
        const float4* s4 = reinterpret_cast<const float4*>(sgeo);
        int n4 = total / 4;  // 960
        for (int t = tid; t < n4; t += BLK) g4[t] = s4[t];
    } else {
        for (int t = tid; t < total; t += BLK) gbase[t] = sgeo[t];
    }
}

// ---------------- host ----------------
static LevelParams make_level_params()
{
    LevelParams lp;
    double pls = exp(log(2048.0 / 16.0) / (double)(NLEV - 1));
    for (int l = 0; l < NLEV; l++) {
        int r = (int)ceil(16.0 * pow(pls, (double)l));
        lp.resf[l]  = (float)r;
        lp.s[l]     = (unsigned)(r + 1);
        long long s = (long long)(r + 1);
        lp.dense[l] = (s * s * s <= (long long)TBL) ? 1u : 0u;
    }
    return lp;
}

extern "C" void kernel_launch(void* const* d_in, const int* in_sizes, int n_in,
                              void* d_out, int out_size)
{
    (void)n_in; (void)out_size;
    const float* xyzs   = (const float*)d_in[0];
    const float* tables = (const float*)d_in[1];
    int N = in_sizes[0] / 3;

    cudaMemcpyToSymbolAsync(cW1, d_in[2], 32 * 64 * sizeof(float), 0,
                            cudaMemcpyDeviceToDevice, 0);
    cudaMemcpyToSymbolAsync(cW2, d_in[3], 64 * 16 * sizeof(float), 0,
                            cudaMemcpyDeviceToDevice, 0);

    LevelParams lp = make_level_params();

    int gridN = (N + BLK - 1) / BLK;
    hashgrid_mlp_kernel<<<gridN, BLK>>>(xyzs, tables, (float*)d_out, N, lp);
}